// round 2
// baseline (speedup 1.0000x reference)
#include <cuda_runtime.h>
#include <math.h>

// Problem constants (fixed by reference)
#define NN 50000
#define EE 800000
#define HH 4
#define CC 64
#define HC 256   // H*C
#define GG 64
#define NEG 0.2f

// Output layout offsets (emb, anomaly, risk, resource, graph_logits)
#define OFF_EMB   0
#define OFF_ANOM  3200000
#define OFF_RISK  3250000
#define OFF_RES   3300000
#define OFF_GLOG  3550000

// ---------------- device scratch (static, no allocation) ----------------
__device__ float g_hbuf[(size_t)NN * HC];   // per-layer h = act @ W   (51.2MB)
__device__ float g_act[(size_t)NN * CC];    // layer activations       (12.8MB)
__device__ float g_als[NN * HH];
__device__ float g_ald[NN * HH];
__device__ int   g_rowstart[NN + 1];
__device__ int   g_cnt[NN];                 // counts -> cursor (reused)
__device__ int   g_csrsrc[EE];
__device__ float g_pooled[GG * CC];

__device__ __forceinline__ float lrelu(float x) { return x > 0.f ? x : NEG * x; }

// ---------------- CSR build ----------------
__global__ void zero_cnt_kernel() {
    int i = blockIdx.x * blockDim.x + threadIdx.x;
    if (i < NN) g_cnt[i] = 0;
}

__global__ void count_kernel(const int* __restrict__ ei) {
    int e = blockIdx.x * blockDim.x + threadIdx.x;
    if (e < EE) atomicAdd(&g_cnt[ei[EE + e]], 1);
}

// single-block exclusive scan of g_cnt -> g_rowstart, also copies into g_cnt (cursor)
__global__ void scan_kernel() {
    __shared__ int wsum[32];
    __shared__ int carry_s;
    if (threadIdx.x == 0) carry_s = 0;
    __syncthreads();
    const int CH = 8192;  // 1024 threads * 8
    for (int base = 0; base < NN; base += CH) {
        int idx0 = base + threadIdx.x * 8;
        int v[8];
        int tot = 0;
#pragma unroll
        for (int i = 0; i < 8; i++) {
            int id = idx0 + i;
            int x = (id < NN) ? g_cnt[id] : 0;
            v[i] = tot;
            tot += x;
        }
        int lane = threadIdx.x & 31, warp = threadIdx.x >> 5;
        int inc = tot;
#pragma unroll
        for (int o = 1; o < 32; o <<= 1) {
            int u = __shfl_up_sync(0xffffffffu, inc, o);
            if (lane >= o) inc += u;
        }
        if (lane == 31) wsum[warp] = inc;
        int excl = inc - tot;
        __syncthreads();
        if (warp == 0) {
            int w = wsum[lane];
            int iw = w;
#pragma unroll
            for (int o = 1; o < 32; o <<= 1) {
                int u = __shfl_up_sync(0xffffffffu, iw, o);
                if (lane >= o) iw += u;
            }
            wsum[lane] = iw - w;
        }
        __syncthreads();
        int off = carry_s + wsum[warp] + excl;
#pragma unroll
        for (int i = 0; i < 8; i++) {
            int id = idx0 + i;
            if (id < NN) {
                int rs = off + v[i];
                g_rowstart[id] = rs;
                g_cnt[id] = rs;  // cursor for fill
            }
        }
        __syncthreads();
        if (threadIdx.x == blockDim.x - 1) carry_s = off + tot;
        __syncthreads();
    }
    if (threadIdx.x == 0) g_rowstart[NN] = EE;
}

__global__ void fill_kernel(const int* __restrict__ ei) {
    int e = blockIdx.x * blockDim.x + threadIdx.x;
    if (e < EE) {
        int dst = ei[EE + e];
        int pos = atomicAdd(&g_cnt[dst], 1);
        g_csrsrc[pos] = ei[e];
    }
}

// ---------------- GEMM: C[M,256] = A[M,K] @ W[K,256] ----------------
template <int K>
__global__ void gemm_kernel(const float* __restrict__ A, const float* __restrict__ W,
                            float* __restrict__ C, int M) {
    const int BM = 64, BK = 64, PAD = 4;
    __shared__ float As[BK][BM + PAD];  // transposed: As[k][m]
    __shared__ float Bs[BK][BM + PAD];  // Bs[k][n]
    int tid = threadIdx.x;
    int tx = tid & 15, ty = tid >> 4;
    int m0 = blockIdx.x * BM, n0 = blockIdx.y * BM;

    float acc[4][4];
#pragma unroll
    for (int i = 0; i < 4; i++)
#pragma unroll
        for (int j = 0; j < 4; j++) acc[i][j] = 0.f;

    for (int k0 = 0; k0 < K; k0 += BK) {
        // load A tile (BM x BK) transposed into As
#pragma unroll
        for (int it = 0; it < 4; it++) {
            int idx = it * 256 + tid;   // 1024 float4 slots
            int row = idx >> 4;         // 16 float4 per row of 64
            int col = (idx & 15) << 2;
            float4 v;
            if (m0 + row < M)
                v = *(const float4*)&A[(size_t)(m0 + row) * K + k0 + col];
            else
                v = make_float4(0.f, 0.f, 0.f, 0.f);
            As[col + 0][row] = v.x;
            As[col + 1][row] = v.y;
            As[col + 2][row] = v.z;
            As[col + 3][row] = v.w;
        }
        // load W tile (BK x 64)
#pragma unroll
        for (int it = 0; it < 4; it++) {
            int idx = it * 256 + tid;
            int k = idx >> 4;
            int col = (idx & 15) << 2;
            *(float4*)&Bs[k][col] = *(const float4*)&W[(size_t)(k0 + k) * HC + n0 + col];
        }
        __syncthreads();
#pragma unroll 8
        for (int k = 0; k < BK; k++) {
            float4 a = *(const float4*)&As[k][ty << 2];
            float4 b = *(const float4*)&Bs[k][tx << 2];
            acc[0][0] += a.x * b.x; acc[0][1] += a.x * b.y; acc[0][2] += a.x * b.z; acc[0][3] += a.x * b.w;
            acc[1][0] += a.y * b.x; acc[1][1] += a.y * b.y; acc[1][2] += a.y * b.z; acc[1][3] += a.y * b.w;
            acc[2][0] += a.z * b.x; acc[2][1] += a.z * b.y; acc[2][2] += a.z * b.z; acc[2][3] += a.z * b.w;
            acc[3][0] += a.w * b.x; acc[3][1] += a.w * b.y; acc[3][2] += a.w * b.z; acc[3][3] += a.w * b.w;
        }
        __syncthreads();
    }
#pragma unroll
    for (int i = 0; i < 4; i++) {
        int m = m0 + (ty << 2) + i;
        if (m < M) {
            float4 o = make_float4(acc[i][0], acc[i][1], acc[i][2], acc[i][3]);
            *(float4*)&C[(size_t)m * HC + n0 + (tx << 2)] = o;
        }
    }
}

// ---------------- per-node attention projections ----------------
// als[n][h] = sum_c h[n][h*64+c] * a_src[h][c]; same for ald.
__global__ void al_kernel(const float* __restrict__ asrc, const float* __restrict__ adst) {
    int warp = threadIdx.x >> 5, lane = threadIdx.x & 31;
    int n = blockIdx.x * 8 + warp;
    if (n >= NN) return;
    const float4* hrow = (const float4*)&g_hbuf[(size_t)n * HC + lane * 8];
    float4 h0 = hrow[0], h1 = hrow[1];
    const float4* a_s = (const float4*)&asrc[lane * 8];
    const float4* a_d = (const float4*)&adst[lane * 8];
    float4 s0 = a_s[0], s1 = a_s[1], d0 = a_d[0], d1 = a_d[1];
    float ps = h0.x * s0.x + h0.y * s0.y + h0.z * s0.z + h0.w * s0.w +
               h1.x * s1.x + h1.y * s1.y + h1.z * s1.z + h1.w * s1.w;
    float pd = h0.x * d0.x + h0.y * d0.y + h0.z * d0.z + h0.w * d0.w +
               h1.x * d1.x + h1.y * d1.y + h1.z * d1.z + h1.w * d1.w;
#pragma unroll
    for (int o = 1; o < 8; o <<= 1) {
        ps += __shfl_xor_sync(0xffffffffu, ps, o);
        pd += __shfl_xor_sync(0xffffffffu, pd, o);
    }
    if ((lane & 7) == 0) {
        int hd = lane >> 3;
        g_als[n * 4 + hd] = ps;
        g_ald[n * 4 + hd] = pd;
    }
}

// ---------------- fused GAT aggregation: softmax + weighted sum + head-mean ----------------
// warp per dst node; lane owns 8 channels (one head each).
__global__ void agg_kernel(const float* __restrict__ bias, float* __restrict__ out, int do_relu) {
    __shared__ int s_src[8][32];
    __shared__ float s_p[8][32 * 4];
    int warp = threadIdx.x >> 5, lane = threadIdx.x & 31;
    int n = blockIdx.x * 8 + warp;
    if (n >= NN) return;
    int hd = lane >> 3;
    float ald_h = g_ald[n * 4 + hd];
    float als_self = g_als[n * 4 + hd];
    float4 aldv = *(const float4*)&g_ald[n * 4];

    // self-loop
    float p = expf(lrelu(als_self + ald_h));
    const float4* selfrow = (const float4*)&g_hbuf[(size_t)n * HC + lane * 8];
    float4 v0 = selfrow[0], v1 = selfrow[1];
    float a0 = p * v0.x, a1 = p * v0.y, a2 = p * v0.z, a3 = p * v0.w;
    float a4 = p * v1.x, a5 = p * v1.y, a6 = p * v1.z, a7 = p * v1.w;
    float den = p;

    int start = g_rowstart[n], end = g_rowstart[n + 1];
    for (int base = start; base < end; base += 32) {
        int cnt = min(32, end - base);
        if (lane < cnt) s_src[warp][lane] = g_csrsrc[base + lane];
        __syncwarp();
        if (lane < cnt) {
            int s = s_src[warp][lane];
            float4 alsv = *(const float4*)&g_als[s * 4];
            s_p[warp][lane * 4 + 0] = expf(lrelu(alsv.x + aldv.x));
            s_p[warp][lane * 4 + 1] = expf(lrelu(alsv.y + aldv.y));
            s_p[warp][lane * 4 + 2] = expf(lrelu(alsv.z + aldv.z));
            s_p[warp][lane * 4 + 3] = expf(lrelu(alsv.w + aldv.w));
        }
        __syncwarp();
#pragma unroll 2
        for (int e = 0; e < cnt; e++) {
            int s = s_src[warp][e];
            float pe = s_p[warp][e * 4 + hd];
            const float4* hr = (const float4*)&g_hbuf[(size_t)s * HC + lane * 8];
            float4 u0 = hr[0], u1 = hr[1];
            a0 += pe * u0.x; a1 += pe * u0.y; a2 += pe * u0.z; a3 += pe * u0.w;
            a4 += pe * u1.x; a5 += pe * u1.y; a6 += pe * u1.z; a7 += pe * u1.w;
            den += pe;
        }
        __syncwarp();
    }
    float inv = 1.f / den;
    a0 *= inv; a1 *= inv; a2 *= inv; a3 *= inv;
    a4 *= inv; a5 *= inv; a6 *= inv; a7 *= inv;
    // head mean: sum over lanes {l, l^8, l^16, l^24}
#pragma unroll
    for (int o = 8; o <= 16; o <<= 1) {
        a0 += __shfl_xor_sync(0xffffffffu, a0, o);
        a1 += __shfl_xor_sync(0xffffffffu, a1, o);
        a2 += __shfl_xor_sync(0xffffffffu, a2, o);
        a3 += __shfl_xor_sync(0xffffffffu, a3, o);
        a4 += __shfl_xor_sync(0xffffffffu, a4, o);
        a5 += __shfl_xor_sync(0xffffffffu, a5, o);
        a6 += __shfl_xor_sync(0xffffffffu, a6, o);
        a7 += __shfl_xor_sync(0xffffffffu, a7, o);
    }
    if (lane < 8) {
        int c = lane * 8;
        float o0 = a0 * 0.25f + bias[c + 0];
        float o1 = a1 * 0.25f + bias[c + 1];
        float o2 = a2 * 0.25f + bias[c + 2];
        float o3 = a3 * 0.25f + bias[c + 3];
        float o4 = a4 * 0.25f + bias[c + 4];
        float o5 = a5 * 0.25f + bias[c + 5];
        float o6 = a6 * 0.25f + bias[c + 6];
        float o7 = a7 * 0.25f + bias[c + 7];
        if (do_relu) {
            o0 = fmaxf(o0, 0.f); o1 = fmaxf(o1, 0.f); o2 = fmaxf(o2, 0.f); o3 = fmaxf(o3, 0.f);
            o4 = fmaxf(o4, 0.f); o5 = fmaxf(o5, 0.f); o6 = fmaxf(o6, 0.f); o7 = fmaxf(o7, 0.f);
        }
        float* op = &out[(size_t)n * CC + c];
        *(float4*)&op[0] = make_float4(o0, o1, o2, o3);
        *(float4*)&op[4] = make_float4(o4, o5, o6, o7);
    }
}

// ---------------- node-level MLP heads ----------------
__global__ void heads_kernel(const float* __restrict__ emb,
                             const float* __restrict__ aw1, const float* __restrict__ ab1,
                             const float* __restrict__ aw2, const float* __restrict__ ab2,
                             const float* __restrict__ rw1, const float* __restrict__ rb1,
                             const float* __restrict__ rw2, const float* __restrict__ rb2,
                             const float* __restrict__ cw1, const float* __restrict__ cb1,
                             const float* __restrict__ cw2, const float* __restrict__ cb2,
                             float* __restrict__ anom, float* __restrict__ risk,
                             float* __restrict__ res) {
    __shared__ float s_aw1[2048], s_rw1[2048], s_cw1[2048];
    __shared__ float s_aw2[32], s_rw2[32], s_cw2[160];
    __shared__ float s_ab1[32], s_rb1[32], s_cb1[32], s_cb2[5];
    __shared__ float s_ab2, s_rb2;
    for (int i = threadIdx.x; i < 2048; i += blockDim.x) {
        s_aw1[i] = aw1[i];
        s_rw1[i] = rw1[i];
        s_cw1[i] = cw1[i];
    }
    for (int i = threadIdx.x; i < 160; i += blockDim.x) s_cw2[i] = cw2[i];
    if (threadIdx.x < 32) {
        s_aw2[threadIdx.x] = aw2[threadIdx.x];
        s_rw2[threadIdx.x] = rw2[threadIdx.x];
        s_ab1[threadIdx.x] = ab1[threadIdx.x];
        s_rb1[threadIdx.x] = rb1[threadIdx.x];
        s_cb1[threadIdx.x] = cb1[threadIdx.x];
    }
    if (threadIdx.x < 5) s_cb2[threadIdx.x] = cb2[threadIdx.x];
    if (threadIdx.x == 0) { s_ab2 = ab2[0]; s_rb2 = rb2[0]; }
    __syncthreads();

    int n = blockIdx.x * blockDim.x + threadIdx.x;
    if (n >= NN) return;
    float r[64];
    const float4* er = (const float4*)&emb[(size_t)n * 64];
#pragma unroll
    for (int i = 0; i < 16; i++) {
        float4 v = er[i];
        r[i * 4 + 0] = v.x; r[i * 4 + 1] = v.y; r[i * 4 + 2] = v.z; r[i * 4 + 3] = v.w;
    }
    float h[32];
    // anomaly
#pragma unroll
    for (int j = 0; j < 32; j++) h[j] = s_ab1[j];
    for (int k = 0; k < 64; k++) {
        float e = r[k];
#pragma unroll
        for (int j = 0; j < 32; j++) h[j] += e * s_aw1[k * 32 + j];
    }
    float o = s_ab2;
#pragma unroll
    for (int j = 0; j < 32; j++) o += fmaxf(h[j], 0.f) * s_aw2[j];
    anom[n] = 1.f / (1.f + expf(-o));
    // risk
#pragma unroll
    for (int j = 0; j < 32; j++) h[j] = s_rb1[j];
    for (int k = 0; k < 64; k++) {
        float e = r[k];
#pragma unroll
        for (int j = 0; j < 32; j++) h[j] += e * s_rw1[k * 32 + j];
    }
    o = s_rb2;
#pragma unroll
    for (int j = 0; j < 32; j++) o += fmaxf(h[j], 0.f) * s_rw2[j];
    risk[n] = 1.f / (1.f + expf(-o));
    // resource
#pragma unroll
    for (int j = 0; j < 32; j++) h[j] = s_cb1[j];
    for (int k = 0; k < 64; k++) {
        float e = r[k];
#pragma unroll
        for (int j = 0; j < 32; j++) h[j] += e * s_cw1[k * 32 + j];
    }
    float o5[5];
#pragma unroll
    for (int t = 0; t < 5; t++) o5[t] = s_cb2[t];
#pragma unroll
    for (int j = 0; j < 32; j++) {
        float hr = fmaxf(h[j], 0.f);
#pragma unroll
        for (int t = 0; t < 5; t++) o5[t] += hr * s_cw2[j * 5 + t];
    }
#pragma unroll
    for (int t = 0; t < 5; t++) res[(size_t)n * 5 + t] = o5[t];
}

// ---------------- pooling (batch is sorted) ----------------
__global__ void zero_pooled_kernel() {
    int i = blockIdx.x * blockDim.x + threadIdx.x;
    if (i < GG * CC) g_pooled[i] = 0.f;
}

__global__ void pool_kernel(const float* __restrict__ emb, const int* __restrict__ batch) {
    int c = threadIdx.x;  // 64 threads
    int n0 = blockIdx.x * 512;
    int n1 = min(n0 + 512, NN);
    if (n0 >= NN) return;
    int cur = batch[n0];
    float acc = 0.f;
    for (int n = n0; n < n1; n++) {
        int g = batch[n];
        if (g != cur) {
            atomicAdd(&g_pooled[cur * 64 + c], acc);
            acc = 0.f;
            cur = g;
        }
        acc += emb[(size_t)n * 64 + c];
    }
    atomicAdd(&g_pooled[cur * 64 + c], acc);
}

__global__ void graph_kernel(const int* __restrict__ batch,
                             const float* __restrict__ gw1, const float* __restrict__ gb1,
                             const float* __restrict__ gw2, const float* __restrict__ gb2,
                             float* __restrict__ out) {
    int g = threadIdx.x;
    if (g >= GG) return;
    int a = 0, b = NN;
    while (a < b) { int m = (a + b) >> 1; if (batch[m] < g) a = m + 1; else b = m; }
    int lb = a;
    a = 0; b = NN;
    while (a < b) { int m = (a + b) >> 1; if (batch[m] < g + 1) a = m + 1; else b = m; }
    int ub = a;
    float cnt = (float)(ub - lb);
    float inv = 1.f / fmaxf(cnt, 1.f);
    float h[32];
#pragma unroll
    for (int j = 0; j < 32; j++) h[j] = gb1[j];
    for (int k = 0; k < 64; k++) {
        float p = g_pooled[g * 64 + k] * inv;
#pragma unroll
        for (int j = 0; j < 32; j++) h[j] += p * gw1[k * 32 + j];
    }
#pragma unroll
    for (int t = 0; t < 4; t++) {
        float o = gb2[t];
#pragma unroll
        for (int j = 0; j < 32; j++) o += fmaxf(h[j], 0.f) * gw2[j * 4 + t];
        out[g * 4 + t] = o;
    }
}

// ---------------- launcher ----------------
extern "C" void kernel_launch(void* const* d_in, const int* in_sizes, int n_in,
                              void* d_out, int out_size) {
    const float* x = (const float*)d_in[0];
    const int* ei = (const int*)d_in[1];
    const int* batch = (const int*)d_in[2];
    const float* W1 = (const float*)d_in[3];
    const float* as1 = (const float*)d_in[4];
    const float* ad1 = (const float*)d_in[5];
    const float* b1 = (const float*)d_in[6];
    const float* W2 = (const float*)d_in[7];
    const float* as2 = (const float*)d_in[8];
    const float* ad2 = (const float*)d_in[9];
    const float* b2 = (const float*)d_in[10];
    const float* W3 = (const float*)d_in[11];
    const float* as3 = (const float*)d_in[12];
    const float* ad3 = (const float*)d_in[13];
    const float* b3 = (const float*)d_in[14];
    const float* aw1 = (const float*)d_in[15];
    const float* ab1 = (const float*)d_in[16];
    const float* aw2 = (const float*)d_in[17];
    const float* ab2 = (const float*)d_in[18];
    const float* rw1 = (const float*)d_in[19];
    const float* rb1 = (const float*)d_in[20];
    const float* rw2 = (const float*)d_in[21];
    const float* rb2 = (const float*)d_in[22];
    const float* cw1 = (const float*)d_in[23];
    const float* cb1 = (const float*)d_in[24];
    const float* cw2 = (const float*)d_in[25];
    const float* cb2 = (const float*)d_in[26];
    const float* gw1 = (const float*)d_in[27];
    const float* gb1 = (const float*)d_in[28];
    const float* gw2 = (const float*)d_in[29];
    const float* gb2 = (const float*)d_in[30];

    float* out = (float*)d_out;
    float* emb = out + OFF_EMB;
    float* anom = out + OFF_ANOM;
    float* risk = out + OFF_RISK;
    float* res = out + OFF_RES;
    float* glog = out + OFF_GLOG;

    float* hbuf_p = nullptr;
    float* act_p = nullptr;
    cudaGetSymbolAddress((void**)&hbuf_p, g_hbuf);
    cudaGetSymbolAddress((void**)&act_p, g_act);

    // CSR build (per-launch, deterministic work)
    zero_cnt_kernel<<<196, 256>>>();
    count_kernel<<<(EE + 255) / 256, 256>>>(ei);
    scan_kernel<<<1, 1024>>>();
    fill_kernel<<<(EE + 255) / 256, 256>>>(ei);

    dim3 ggrid((NN + 63) / 64, 4);

    // Layer 1
    gemm_kernel<128><<<ggrid, 256>>>(x, W1, hbuf_p, NN);
    al_kernel<<<NN / 8, 256>>>(as1, ad1);
    agg_kernel<<<NN / 8, 256>>>(b1, act_p, 1);
    // Layer 2
    gemm_kernel<64><<<ggrid, 256>>>(act_p, W2, hbuf_p, NN);
    al_kernel<<<NN / 8, 256>>>(as2, ad2);
    agg_kernel<<<NN / 8, 256>>>(b2, act_p, 1);
    // Layer 3 -> emb (in d_out)
    gemm_kernel<64><<<ggrid, 256>>>(act_p, W3, hbuf_p, NN);
    al_kernel<<<NN / 8, 256>>>(as3, ad3);
    agg_kernel<<<NN / 8, 256>>>(b3, emb, 0);

    // MLP heads
    heads_kernel<<<(NN + 127) / 128, 128>>>(emb, aw1, ab1, aw2, ab2, rw1, rb1, rw2, rb2,
                                            cw1, cb1, cw2, cb2, anom, risk, res);
    // Pooling + graph MLP
    zero_pooled_kernel<<<16, 256>>>();
    pool_kernel<<<(NN + 511) / 512, 64>>>(emb, batch);
    graph_kernel<<<1, 64>>>(batch, gw1, gb1, gw2, gb2, glog);
}

// round 4
// speedup vs baseline: 1.7936x; 1.7936x over previous
#include <cuda_runtime.h>
#include <cuda_fp16.h>
#include <math.h>

// Problem constants (fixed by reference)
#define NN 50000
#define EE 800000
#define HH 4
#define CC 64
#define HC 256   // H*C
#define GG 64
#define NEG 0.2f

// Output layout offsets (emb, anomaly, risk, resource, graph_logits)
#define OFF_EMB   0
#define OFF_ANOM  3200000
#define OFF_RISK  3250000
#define OFF_RES   3300000
#define OFF_GLOG  3550000

// ---------------- device scratch (static, no allocation) ----------------
__device__ __half g_hbuf_h[(size_t)NN * HC];  // per-layer h = act @ W (fp16, 25.6MB)
__device__ float g_act[(size_t)NN * CC];      // layer activations (fp32)
__device__ float g_als[NN * HH];
__device__ float g_ald[NN * HH];
__device__ int   g_rowstart[NN + 1];
__device__ int   g_cnt[NN];                   // counts -> cursor (reused)
__device__ int   g_csrsrc[EE];
__device__ float g_pooled[GG * CC];

__device__ __forceinline__ float lrelu(float x) { return x > 0.f ? x : NEG * x; }

// ---------------- CSR build ----------------
__global__ void zero_cnt_kernel() {
    int i = blockIdx.x * blockDim.x + threadIdx.x;
    if (i < NN) g_cnt[i] = 0;
}

__global__ void count_kernel(const int* __restrict__ ei) {
    int e = blockIdx.x * blockDim.x + threadIdx.x;
    if (e < EE) atomicAdd(&g_cnt[ei[EE + e]], 1);
}

// single-block exclusive scan of g_cnt -> g_rowstart, also copies into g_cnt (cursor)
__global__ void scan_kernel() {
    __shared__ int wsum[32];
    __shared__ int carry_s;
    if (threadIdx.x == 0) carry_s = 0;
    __syncthreads();
    const int CH = 8192;  // 1024 threads * 8
    for (int base = 0; base < NN; base += CH) {
        int idx0 = base + threadIdx.x * 8;
        int v[8];
        int tot = 0;
#pragma unroll
        for (int i = 0; i < 8; i++) {
            int id = idx0 + i;
            int x = (id < NN) ? g_cnt[id] : 0;
            v[i] = tot;
            tot += x;
        }
        int lane = threadIdx.x & 31, warp = threadIdx.x >> 5;
        int inc = tot;
#pragma unroll
        for (int o = 1; o < 32; o <<= 1) {
            int u = __shfl_up_sync(0xffffffffu, inc, o);
            if (lane >= o) inc += u;
        }
        if (lane == 31) wsum[warp] = inc;
        int excl = inc - tot;
        __syncthreads();
        if (warp == 0) {
            int w = wsum[lane];
            int iw = w;
#pragma unroll
            for (int o = 1; o < 32; o <<= 1) {
                int u = __shfl_up_sync(0xffffffffu, iw, o);
                if (lane >= o) iw += u;
            }
            wsum[lane] = iw - w;
        }
        __syncthreads();
        int off = carry_s + wsum[warp] + excl;
#pragma unroll
        for (int i = 0; i < 8; i++) {
            int id = idx0 + i;
            if (id < NN) {
                int rs = off + v[i];
                g_rowstart[id] = rs;
                g_cnt[id] = rs;  // cursor for fill
            }
        }
        __syncthreads();
        if (threadIdx.x == blockDim.x - 1) carry_s = off + tot;
        __syncthreads();
    }
    if (threadIdx.x == 0) g_rowstart[NN] = EE;
}

__global__ void fill_kernel(const int* __restrict__ ei) {
    int e = blockIdx.x * blockDim.x + threadIdx.x;
    if (e < EE) {
        int dst = ei[EE + e];
        int pos = atomicAdd(&g_cnt[dst], 1);
        g_csrsrc[pos] = ei[e];
    }
}

// ---------------- GEMM: C[M,256] = A[M,K] @ W[K,256], output fp16 ----------------
template <int K>
__global__ void gemm_kernel(const float* __restrict__ A, const float* __restrict__ W,
                            __half* __restrict__ Ch, int M) {
    const int BM = 64, BK = 64, PAD = 4;
    __shared__ float As[BK][BM + PAD];  // transposed: As[k][m]
    __shared__ float Bs[BK][BM + PAD];  // Bs[k][n]
    int tid = threadIdx.x;
    int tx = tid & 15, ty = tid >> 4;
    int m0 = blockIdx.x * BM, n0 = blockIdx.y * BM;

    float acc[4][4];
#pragma unroll
    for (int i = 0; i < 4; i++)
#pragma unroll
        for (int j = 0; j < 4; j++) acc[i][j] = 0.f;

    for (int k0 = 0; k0 < K; k0 += BK) {
        // load A tile (BM x BK) transposed into As
#pragma unroll
        for (int it = 0; it < 4; it++) {
            int idx = it * 256 + tid;   // 1024 float4 slots
            int row = idx >> 4;         // 16 float4 per row of 64
            int col = (idx & 15) << 2;
            float4 v;
            if (m0 + row < M)
                v = *(const float4*)&A[(size_t)(m0 + row) * K + k0 + col];
            else
                v = make_float4(0.f, 0.f, 0.f, 0.f);
            As[col + 0][row] = v.x;
            As[col + 1][row] = v.y;
            As[col + 2][row] = v.z;
            As[col + 3][row] = v.w;
        }
        // load W tile (BK x 64)
#pragma unroll
        for (int it = 0; it < 4; it++) {
            int idx = it * 256 + tid;
            int k = idx >> 4;
            int col = (idx & 15) << 2;
            *(float4*)&Bs[k][col] = *(const float4*)&W[(size_t)(k0 + k) * HC + n0 + col];
        }
        __syncthreads();
#pragma unroll 8
        for (int k = 0; k < BK; k++) {
            float4 a = *(const float4*)&As[k][ty << 2];
            float4 b = *(const float4*)&Bs[k][tx << 2];
            acc[0][0] += a.x * b.x; acc[0][1] += a.x * b.y; acc[0][2] += a.x * b.z; acc[0][3] += a.x * b.w;
            acc[1][0] += a.y * b.x; acc[1][1] += a.y * b.y; acc[1][2] += a.y * b.z; acc[1][3] += a.y * b.w;
            acc[2][0] += a.z * b.x; acc[2][1] += a.z * b.y; acc[2][2] += a.z * b.z; acc[2][3] += a.z * b.w;
            acc[3][0] += a.w * b.x; acc[3][1] += a.w * b.y; acc[3][2] += a.w * b.z; acc[3][3] += a.w * b.w;
        }
        __syncthreads();
    }
#pragma unroll
    for (int i = 0; i < 4; i++) {
        int m = m0 + (ty << 2) + i;
        if (m < M) {
            union { uint2 u; __half2 h[2]; } pk;
            pk.h[0] = __floats2half2_rn(acc[i][0], acc[i][1]);
            pk.h[1] = __floats2half2_rn(acc[i][2], acc[i][3]);
            *(uint2*)&Ch[(size_t)m * HC + n0 + (tx << 2)] = pk.u;
        }
    }
}

// ---------------- per-node attention projections (reads fp16 h) ----------------
__global__ void al_kernel(const float* __restrict__ asrc, const float* __restrict__ adst) {
    int warp = threadIdx.x >> 5, lane = threadIdx.x & 31;
    int n = blockIdx.x * 8 + warp;
    if (n >= NN) return;
    int4 raw = *(const int4*)&g_hbuf_h[(size_t)n * HC + lane * 8];
    const __half2* hp = (const __half2*)&raw;
    float2 f0 = __half22float2(hp[0]);
    float2 f1 = __half22float2(hp[1]);
    float2 f2 = __half22float2(hp[2]);
    float2 f3 = __half22float2(hp[3]);
    const float4* a_s = (const float4*)&asrc[lane * 8];
    const float4* a_d = (const float4*)&adst[lane * 8];
    float4 s0 = a_s[0], s1 = a_s[1], d0 = a_d[0], d1 = a_d[1];
    float ps = f0.x * s0.x + f0.y * s0.y + f1.x * s0.z + f1.y * s0.w +
               f2.x * s1.x + f2.y * s1.y + f3.x * s1.z + f3.y * s1.w;
    float pd = f0.x * d0.x + f0.y * d0.y + f1.x * d0.z + f1.y * d0.w +
               f2.x * d1.x + f2.y * d1.y + f3.x * d1.z + f3.y * d1.w;
#pragma unroll
    for (int o = 1; o < 8; o <<= 1) {
        ps += __shfl_xor_sync(0xffffffffu, ps, o);
        pd += __shfl_xor_sync(0xffffffffu, pd, o);
    }
    if ((lane & 7) == 0) {
        int hd = lane >> 3;
        g_als[n * 4 + hd] = ps;
        g_ald[n * 4 + hd] = pd;
    }
}

// ---------------- fused GAT aggregation: softmax + weighted sum + head-mean ----------------
// warp per dst node; lane owns 8 channels (one head each). h gathered as fp16.
__global__ void agg_kernel(const float* __restrict__ bias, float* __restrict__ out, int do_relu) {
    __shared__ int s_src[8][32];
    __shared__ float s_p[8][32 * 4];
    int warp = threadIdx.x >> 5, lane = threadIdx.x & 31;
    int n = blockIdx.x * 8 + warp;
    if (n >= NN) return;
    int hd = lane >> 3;
    float ald_h = g_ald[n * 4 + hd];
    float als_self = g_als[n * 4 + hd];
    float4 aldv = *(const float4*)&g_ald[n * 4];

    // self-loop
    float p = expf(lrelu(als_self + ald_h));
    int4 sraw = *(const int4*)&g_hbuf_h[(size_t)n * HC + lane * 8];
    const __half2* sp2 = (const __half2*)&sraw;
    float2 sf0 = __half22float2(sp2[0]);
    float2 sf1 = __half22float2(sp2[1]);
    float2 sf2 = __half22float2(sp2[2]);
    float2 sf3 = __half22float2(sp2[3]);
    float a0 = p * sf0.x, a1 = p * sf0.y, a2 = p * sf1.x, a3 = p * sf1.y;
    float a4 = p * sf2.x, a5 = p * sf2.y, a6 = p * sf3.x, a7 = p * sf3.y;
    float den = p;

    int start = g_rowstart[n], end = g_rowstart[n + 1];
    for (int base = start; base < end; base += 32) {
        int cnt = min(32, end - base);
        if (lane < cnt) s_src[warp][lane] = g_csrsrc[base + lane];
        __syncwarp();
        if (lane < cnt) {
            int s = s_src[warp][lane];
            float4 alsv = *(const float4*)&g_als[s * 4];
            s_p[warp][lane * 4 + 0] = expf(lrelu(alsv.x + aldv.x));
            s_p[warp][lane * 4 + 1] = expf(lrelu(alsv.y + aldv.y));
            s_p[warp][lane * 4 + 2] = expf(lrelu(alsv.z + aldv.z));
            s_p[warp][lane * 4 + 3] = expf(lrelu(alsv.w + aldv.w));
        }
        __syncwarp();
#pragma unroll 4
        for (int e = 0; e < cnt; e++) {
            int s = s_src[warp][e];
            float pe = s_p[warp][e * 4 + hd];
            int4 raw = *(const int4*)&g_hbuf_h[(size_t)s * HC + lane * 8];
            const __half2* hp = (const __half2*)&raw;
            float2 u0 = __half22float2(hp[0]);
            float2 u1 = __half22float2(hp[1]);
            float2 u2 = __half22float2(hp[2]);
            float2 u3 = __half22float2(hp[3]);
            a0 += pe * u0.x; a1 += pe * u0.y; a2 += pe * u1.x; a3 += pe * u1.y;
            a4 += pe * u2.x; a5 += pe * u2.y; a6 += pe * u3.x; a7 += pe * u3.y;
            den += pe;
        }
        __syncwarp();
    }
    float inv = 1.f / den;
    a0 *= inv; a1 *= inv; a2 *= inv; a3 *= inv;
    a4 *= inv; a5 *= inv; a6 *= inv; a7 *= inv;
    // head mean: sum over lanes {l, l^8, l^16, l^24}
#pragma unroll
    for (int o = 8; o <= 16; o <<= 1) {
        a0 += __shfl_xor_sync(0xffffffffu, a0, o);
        a1 += __shfl_xor_sync(0xffffffffu, a1, o);
        a2 += __shfl_xor_sync(0xffffffffu, a2, o);
        a3 += __shfl_xor_sync(0xffffffffu, a3, o);
        a4 += __shfl_xor_sync(0xffffffffu, a4, o);
        a5 += __shfl_xor_sync(0xffffffffu, a5, o);
        a6 += __shfl_xor_sync(0xffffffffu, a6, o);
        a7 += __shfl_xor_sync(0xffffffffu, a7, o);
    }
    if (lane < 8) {
        int c = lane * 8;
        float o0 = a0 * 0.25f + bias[c + 0];
        float o1 = a1 * 0.25f + bias[c + 1];
        float o2 = a2 * 0.25f + bias[c + 2];
        float o3 = a3 * 0.25f + bias[c + 3];
        float o4 = a4 * 0.25f + bias[c + 4];
        float o5 = a5 * 0.25f + bias[c + 5];
        float o6 = a6 * 0.25f + bias[c + 6];
        float o7 = a7 * 0.25f + bias[c + 7];
        if (do_relu) {
            o0 = fmaxf(o0, 0.f); o1 = fmaxf(o1, 0.f); o2 = fmaxf(o2, 0.f); o3 = fmaxf(o3, 0.f);
            o4 = fmaxf(o4, 0.f); o5 = fmaxf(o5, 0.f); o6 = fmaxf(o6, 0.f); o7 = fmaxf(o7, 0.f);
        }
        float* op = &out[(size_t)n * CC + c];
        *(float4*)&op[0] = make_float4(o0, o1, o2, o3);
        *(float4*)&op[4] = make_float4(o4, o5, o6, o7);
    }
}

// ---------------- node-level MLP heads ----------------
__global__ void heads_kernel(const float* __restrict__ emb,
                             const float* __restrict__ aw1, const float* __restrict__ ab1,
                             const float* __restrict__ aw2, const float* __restrict__ ab2,
                             const float* __restrict__ rw1, const float* __restrict__ rb1,
                             const float* __restrict__ rw2, const float* __restrict__ rb2,
                             const float* __restrict__ cw1, const float* __restrict__ cb1,
                             const float* __restrict__ cw2, const float* __restrict__ cb2,
                             float* __restrict__ anom, float* __restrict__ risk,
                             float* __restrict__ res) {
    __shared__ float s_aw1[2048], s_rw1[2048], s_cw1[2048];
    __shared__ float s_aw2[32], s_rw2[32], s_cw2[160];
    __shared__ float s_ab1[32], s_rb1[32], s_cb1[32], s_cb2[5];
    __shared__ float s_ab2, s_rb2;
    for (int i = threadIdx.x; i < 2048; i += blockDim.x) {
        s_aw1[i] = aw1[i];
        s_rw1[i] = rw1[i];
        s_cw1[i] = cw1[i];
    }
    for (int i = threadIdx.x; i < 160; i += blockDim.x) s_cw2[i] = cw2[i];
    if (threadIdx.x < 32) {
        s_aw2[threadIdx.x] = aw2[threadIdx.x];
        s_rw2[threadIdx.x] = rw2[threadIdx.x];
        s_ab1[threadIdx.x] = ab1[threadIdx.x];
        s_rb1[threadIdx.x] = rb1[threadIdx.x];
        s_cb1[threadIdx.x] = cb1[threadIdx.x];
    }
    if (threadIdx.x < 5) s_cb2[threadIdx.x] = cb2[threadIdx.x];
    if (threadIdx.x == 0) { s_ab2 = ab2[0]; s_rb2 = rb2[0]; }
    __syncthreads();

    int n = blockIdx.x * blockDim.x + threadIdx.x;
    if (n >= NN) return;
    float r[64];
    const float4* er = (const float4*)&emb[(size_t)n * 64];
#pragma unroll
    for (int i = 0; i < 16; i++) {
        float4 v = er[i];
        r[i * 4 + 0] = v.x; r[i * 4 + 1] = v.y; r[i * 4 + 2] = v.z; r[i * 4 + 3] = v.w;
    }
    float h[32];
    // anomaly
#pragma unroll
    for (int j = 0; j < 32; j++) h[j] = s_ab1[j];
    for (int k = 0; k < 64; k++) {
        float e = r[k];
#pragma unroll
        for (int j = 0; j < 32; j++) h[j] += e * s_aw1[k * 32 + j];
    }
    float o = s_ab2;
#pragma unroll
    for (int j = 0; j < 32; j++) o += fmaxf(h[j], 0.f) * s_aw2[j];
    anom[n] = 1.f / (1.f + expf(-o));
    // risk
#pragma unroll
    for (int j = 0; j < 32; j++) h[j] = s_rb1[j];
    for (int k = 0; k < 64; k++) {
        float e = r[k];
#pragma unroll
        for (int j = 0; j < 32; j++) h[j] += e * s_rw1[k * 32 + j];
    }
    o = s_rb2;
#pragma unroll
    for (int j = 0; j < 32; j++) o += fmaxf(h[j], 0.f) * s_rw2[j];
    risk[n] = 1.f / (1.f + expf(-o));
    // resource
#pragma unroll
    for (int j = 0; j < 32; j++) h[j] = s_cb1[j];
    for (int k = 0; k < 64; k++) {
        float e = r[k];
#pragma unroll
        for (int j = 0; j < 32; j++) h[j] += e * s_cw1[k * 32 + j];
    }
    float o5[5];
#pragma unroll
    for (int t = 0; t < 5; t++) o5[t] = s_cb2[t];
#pragma unroll
    for (int j = 0; j < 32; j++) {
        float hr = fmaxf(h[j], 0.f);
#pragma unroll
        for (int t = 0; t < 5; t++) o5[t] += hr * s_cw2[j * 5 + t];
    }
#pragma unroll
    for (int t = 0; t < 5; t++) res[(size_t)n * 5 + t] = o5[t];
}

// ---------------- pooling (batch is sorted) ----------------
__global__ void zero_pooled_kernel() {
    int i = blockIdx.x * blockDim.x + threadIdx.x;
    if (i < GG * CC) g_pooled[i] = 0.f;
}

__global__ void pool_kernel(const float* __restrict__ emb, const int* __restrict__ batch) {
    int c = threadIdx.x;  // 64 threads
    int n0 = blockIdx.x * 512;
    int n1 = min(n0 + 512, NN);
    if (n0 >= NN) return;
    int cur = batch[n0];
    float acc = 0.f;
    for (int n = n0; n < n1; n++) {
        int g = batch[n];
        if (g != cur) {
            atomicAdd(&g_pooled[cur * 64 + c], acc);
            acc = 0.f;
            cur = g;
        }
        acc += emb[(size_t)n * 64 + c];
    }
    atomicAdd(&g_pooled[cur * 64 + c], acc);
}

__global__ void graph_kernel(const int* __restrict__ batch,
                             const float* __restrict__ gw1, const float* __restrict__ gb1,
                             const float* __restrict__ gw2, const float* __restrict__ gb2,
                             float* __restrict__ out) {
    int g = threadIdx.x;
    if (g >= GG) return;
    int a = 0, b = NN;
    while (a < b) { int m = (a + b) >> 1; if (batch[m] < g) a = m + 1; else b = m; }
    int lb = a;
    a = 0; b = NN;
    while (a < b) { int m = (a + b) >> 1; if (batch[m] < g + 1) a = m + 1; else b = m; }
    int ub = a;
    float cnt = (float)(ub - lb);
    float inv = 1.f / fmaxf(cnt, 1.f);
    float h[32];
#pragma unroll
    for (int j = 0; j < 32; j++) h[j] = gb1[j];
    for (int k = 0; k < 64; k++) {
        float p = g_pooled[g * 64 + k] * inv;
#pragma unroll
        for (int j = 0; j < 32; j++) h[j] += p * gw1[k * 32 + j];
    }
#pragma unroll
    for (int t = 0; t < 4; t++) {
        float o = gb2[t];
#pragma unroll
        for (int j = 0; j < 32; j++) o += fmaxf(h[j], 0.f) * gw2[j * 4 + t];
        out[g * 4 + t] = o;
    }
}

// ---------------- launcher ----------------
extern "C" void kernel_launch(void* const* d_in, const int* in_sizes, int n_in,
                              void* d_out, int out_size) {
    const float* x = (const float*)d_in[0];
    const int* ei = (const int*)d_in[1];
    const int* batch = (const int*)d_in[2];
    const float* W1 = (const float*)d_in[3];
    const float* as1 = (const float*)d_in[4];
    const float* ad1 = (const float*)d_in[5];
    const float* b1 = (const float*)d_in[6];
    const float* W2 = (const float*)d_in[7];
    const float* as2 = (const float*)d_in[8];
    const float* ad2 = (const float*)d_in[9];
    const float* b2 = (const float*)d_in[10];
    const float* W3 = (const float*)d_in[11];
    const float* as3 = (const float*)d_in[12];
    const float* ad3 = (const float*)d_in[13];
    const float* b3 = (const float*)d_in[14];
    const float* aw1 = (const float*)d_in[15];
    const float* ab1 = (const float*)d_in[16];
    const float* aw2 = (const float*)d_in[17];
    const float* ab2 = (const float*)d_in[18];
    const float* rw1 = (const float*)d_in[19];
    const float* rb1 = (const float*)d_in[20];
    const float* rw2 = (const float*)d_in[21];
    const float* rb2 = (const float*)d_in[22];
    const float* cw1 = (const float*)d_in[23];
    const float* cb1 = (const float*)d_in[24];
    const float* cw2 = (const float*)d_in[25];
    const float* cb2 = (const float*)d_in[26];
    const float* gw1 = (const float*)d_in[27];
    const float* gb1 = (const float*)d_in[28];
    const float* gw2 = (const float*)d_in[29];
    const float* gb2 = (const float*)d_in[30];

    float* out = (float*)d_out;
    float* emb = out + OFF_EMB;
    float* anom = out + OFF_ANOM;
    float* risk = out + OFF_RISK;
    float* res = out + OFF_RES;
    float* glog = out + OFF_GLOG;

    __half* hbuf_p = nullptr;
    float* act_p = nullptr;
    cudaGetSymbolAddress((void**)&hbuf_p, g_hbuf_h);
    cudaGetSymbolAddress((void**)&act_p, g_act);

    // CSR build (per-launch, deterministic work)
    zero_cnt_kernel<<<196, 256>>>();
    count_kernel<<<(EE + 255) / 256, 256>>>(ei);
    scan_kernel<<<1, 1024>>>();
    fill_kernel<<<(EE + 255) / 256, 256>>>(ei);

    dim3 ggrid((NN + 63) / 64, 4);

    // Layer 1
    gemm_kernel<128><<<ggrid, 256>>>(x, W1, hbuf_p, NN);
    al_kernel<<<NN / 8, 256>>>(as1, ad1);
    agg_kernel<<<NN / 8, 256>>>(b1, act_p, 1);
    // Layer 2
    gemm_kernel<64><<<ggrid, 256>>>(act_p, W2, hbuf_p, NN);
    al_kernel<<<NN / 8, 256>>>(as2, ad2);
    agg_kernel<<<NN / 8, 256>>>(b2, act_p, 1);
    // Layer 3 -> emb (in d_out)
    gemm_kernel<64><<<ggrid, 256>>>(act_p, W3, hbuf_p, NN);
    al_kernel<<<NN / 8, 256>>>(as3, ad3);
    agg_kernel<<<NN / 8, 256>>>(b3, emb, 0);

    // MLP heads
    heads_kernel<<<(NN + 127) / 128, 128>>>(emb, aw1, ab1, aw2, ab2, rw1, rb1, rw2, rb2,
                                            cw1, cb1, cw2, cb2, anom, risk, res);
    // Pooling + graph MLP
    zero_pooled_kernel<<<16, 256>>>();
    pool_kernel<<<(NN + 511) / 512, 64>>>(emb, batch);
    graph_kernel<<<1, 64>>>(batch, gw1, gb1, gw2, gb2, glog);
}

// round 8
// speedup vs baseline: 1.9039x; 1.0615x over previous
#include <cuda_runtime.h>
#include <cuda_fp16.h>
#include <mma.h>
#include <math.h>

// Problem constants (fixed by reference)
#define NN 50000
#define EE 800000
#define HH 4
#define CC 64
#define HC 256   // H*C
#define GG 64
#define NEG 0.2f

// Output layout offsets (emb, anomaly, risk, resource, graph_logits)
#define OFF_EMB   0
#define OFF_ANOM  3200000
#define OFF_RISK  3250000
#define OFF_RES   3300000
#define OFF_GLOG  3550000

// ---------------- device scratch (static, no allocation) ----------------
__device__ __half g_hbuf_h[(size_t)NN * HC];  // per-layer h = act @ W (fp16, 25.6MB)
__device__ __half g_acth[(size_t)NN * CC];    // layer activations (fp16, 6.4MB)
__device__ __half g_xh[(size_t)NN * 128];     // fp16 copy of input x (12.8MB)
__device__ __half g_w1h[128 * HC];
__device__ __half g_w2h[CC * HC];
__device__ __half g_w3h[CC * HC];
__device__ float g_als[NN * HH];
__device__ float g_ald[NN * HH];
__device__ int   g_rowstart[NN + 1];
__device__ int   g_cnt[NN];                   // counts -> cursor (reused)
__device__ int   g_csrsrc[EE];
__device__ float g_pooled[GG * CC];

__device__ __forceinline__ float lrelu(float x) { return x > 0.f ? x : NEG * x; }

// ---------------- fp32 -> fp16 convert ----------------
__global__ void f2h_kernel(const float* __restrict__ src, __half* __restrict__ dst, int n4) {
    int i = blockIdx.x * blockDim.x + threadIdx.x;
    if (i < n4) {
        float4 v = *(const float4*)&src[i * 4];
        union { uint2 u; __half2 h[2]; } pk;
        pk.h[0] = __floats2half2_rn(v.x, v.y);
        pk.h[1] = __floats2half2_rn(v.z, v.w);
        *(uint2*)&dst[i * 4] = pk.u;
    }
}

// ---------------- CSR build ----------------
__global__ void zero_cnt_kernel() {
    int i = blockIdx.x * blockDim.x + threadIdx.x;
    if (i < NN) g_cnt[i] = 0;
}

__global__ void count_kernel(const int* __restrict__ ei) {
    int e = blockIdx.x * blockDim.x + threadIdx.x;
    if (e < EE) atomicAdd(&g_cnt[ei[EE + e]], 1);
}

// single-block exclusive scan of g_cnt -> g_rowstart, also copies into g_cnt (cursor)
__global__ void scan_kernel() {
    __shared__ int wsum[32];
    __shared__ int carry_s;
    if (threadIdx.x == 0) carry_s = 0;
    __syncthreads();
    const int CH = 8192;  // 1024 threads * 8
    for (int base = 0; base < NN; base += CH) {
        int idx0 = base + threadIdx.x * 8;
        int v[8];
        int tot = 0;
#pragma unroll
        for (int i = 0; i < 8; i++) {
            int id = idx0 + i;
            int x = (id < NN) ? g_cnt[id] : 0;
            v[i] = tot;
            tot += x;
        }
        int lane = threadIdx.x & 31, warp = threadIdx.x >> 5;
        int inc = tot;
#pragma unroll
        for (int o = 1; o < 32; o <<= 1) {
            int u = __shfl_up_sync(0xffffffffu, inc, o);
            if (lane >= o) inc += u;
        }
        if (lane == 31) wsum[warp] = inc;
        int excl = inc - tot;
        __syncthreads();
        if (warp == 0) {
            int w = wsum[lane];
            int iw = w;
#pragma unroll
            for (int o = 1; o < 32; o <<= 1) {
                int u = __shfl_up_sync(0xffffffffu, iw, o);
                if (lane >= o) iw += u;
            }
            wsum[lane] = iw - w;
        }
        __syncthreads();
        int off = carry_s + wsum[warp] + excl;
#pragma unroll
        for (int i = 0; i < 8; i++) {
            int id = idx0 + i;
            if (id < NN) {
                int rs = off + v[i];
                g_rowstart[id] = rs;
                g_cnt[id] = rs;  // cursor for fill
            }
        }
        __syncthreads();
        if (threadIdx.x == blockDim.x - 1) carry_s = off + tot;
        __syncthreads();
    }
    if (threadIdx.x == 0) g_rowstart[NN] = EE;
}

__global__ void fill_kernel(const int* __restrict__ ei) {
    int e = blockIdx.x * blockDim.x + threadIdx.x;
    if (e < EE) {
        int dst = ei[EE + e];
        int pos = atomicAdd(&g_cnt[dst], 1);
        g_csrsrc[pos] = ei[e];
    }
}

// ---------------- tensor-core GEMM: C[M,256] = A[M,K]h @ W[K,256]h, fp32 accum, fp16 out ----
// grid: (ceil(M/128), 4). block: 256 threads = 8 warps, each warp does 16 rows x 64 cols.
template <int K>
__global__ void gemm_wmma_kernel(const __half* __restrict__ A, const __half* __restrict__ W,
                                 __half* __restrict__ Ch, int M) {
    using namespace nvcuda;
    __shared__ float stage[8][16 * 72];
    int w = threadIdx.x >> 5, lane = threadIdx.x & 31;
    int row0 = blockIdx.x * 128 + w * 16;
    if (row0 >= M) return;
    int n0 = blockIdx.y * 64;

    wmma::fragment<wmma::accumulator, 16, 16, 16, float> acc[4];
#pragma unroll
    for (int j = 0; j < 4; j++) wmma::fill_fragment(acc[j], 0.f);

    wmma::fragment<wmma::matrix_a, 16, 16, 16, __half, wmma::row_major> af;
    wmma::fragment<wmma::matrix_b, 16, 16, 16, __half, wmma::row_major> bf;

#pragma unroll
    for (int k0 = 0; k0 < K; k0 += 16) {
        wmma::load_matrix_sync(af, A + (size_t)row0 * K + k0, K);
#pragma unroll
        for (int j = 0; j < 4; j++) {
            wmma::load_matrix_sync(bf, W + (size_t)k0 * HC + n0 + j * 16, HC);
            wmma::mma_sync(acc[j], af, bf, acc[j]);
        }
    }
#pragma unroll
    for (int j = 0; j < 4; j++)
        wmma::store_matrix_sync(&stage[w][j * 16], acc[j], 72, wmma::mem_row_major);
    __syncwarp();
    // convert 16x64 f32 staging -> fp16 global
#pragma unroll
    for (int i = lane; i < 512; i += 32) {  // 512 half2 slots
        int r = i >> 5, c2 = i & 31;
        __half2 hv = __floats2half2_rn(stage[w][r * 72 + c2 * 2], stage[w][r * 72 + c2 * 2 + 1]);
        *(__half2*)&Ch[(size_t)(row0 + r) * HC + n0 + c2 * 2] = hv;
    }
}

// ---------------- per-node attention projections (reads fp16 h) ----------------
__global__ void al_kernel(const float* __restrict__ asrc, const float* __restrict__ adst) {
    int warp = threadIdx.x >> 5, lane = threadIdx.x & 31;
    int n = blockIdx.x * 8 + warp;
    if (n >= NN) return;
    int4 raw = *(const int4*)&g_hbuf_h[(size_t)n * HC + lane * 8];
    const __half2* hp = (const __half2*)&raw;
    float2 f0 = __half22float2(hp[0]);
    float2 f1 = __half22float2(hp[1]);
    float2 f2 = __half22float2(hp[2]);
    float2 f3 = __half22float2(hp[3]);
    const float4* a_s = (const float4*)&asrc[lane * 8];
    const float4* a_d = (const float4*)&adst[lane * 8];
    float4 s0 = a_s[0], s1 = a_s[1], d0 = a_d[0], d1 = a_d[1];
    float ps = f0.x * s0.x + f0.y * s0.y + f1.x * s0.z + f1.y * s0.w +
               f2.x * s1.x + f2.y * s1.y + f3.x * s1.z + f3.y * s1.w;
    float pd = f0.x * d0.x + f0.y * d0.y + f1.x * d0.z + f1.y * d0.w +
               f2.x * d1.x + f2.y * d1.y + f3.x * d1.z + f3.y * d1.w;
#pragma unroll
    for (int o = 1; o < 8; o <<= 1) {
        ps += __shfl_xor_sync(0xffffffffu, ps, o);
        pd += __shfl_xor_sync(0xffffffffu, pd, o);
    }
    if ((lane & 7) == 0) {
        int hd = lane >> 3;
        g_als[n * 4 + hd] = ps;
        g_ald[n * 4 + hd] = pd;
    }
}

// ---------------- fused GAT aggregation: softmax + weighted sum + head-mean ----------------
// warp per dst node; lane owns 8 channels (one head each). h gathered as fp16.
// FINAL=0: write fp16 act (g_acth); FINAL=1: write fp32 emb.
template <int FINAL>
__global__ void agg_kernel(const float* __restrict__ bias, float* __restrict__ outf,
                           __half* __restrict__ outh, int do_relu) {
    __shared__ int s_src[8][32];
    __shared__ float s_p[8][32 * 4];
    int warp = threadIdx.x >> 5, lane = threadIdx.x & 31;
    int n = blockIdx.x * 8 + warp;
    if (n >= NN) return;
    int hd = lane >> 3;
    float ald_h = g_ald[n * 4 + hd];
    float als_self = g_als[n * 4 + hd];
    float4 aldv = *(const float4*)&g_ald[n * 4];

    // self-loop
    float p = __expf(lrelu(als_self + ald_h));
    int4 sraw = *(const int4*)&g_hbuf_h[(size_t)n * HC + lane * 8];
    const __half2* sp2 = (const __half2*)&sraw;
    float2 sf0 = __half22float2(sp2[0]);
    float2 sf1 = __half22float2(sp2[1]);
    float2 sf2 = __half22float2(sp2[2]);
    float2 sf3 = __half22float2(sp2[3]);
    float a0 = p * sf0.x, a1 = p * sf0.y, a2 = p * sf1.x, a3 = p * sf1.y;
    float a4 = p * sf2.x, a5 = p * sf2.y, a6 = p * sf3.x, a7 = p * sf3.y;
    float den = p;

    int start = g_rowstart[n], end = g_rowstart[n + 1];
    for (int base = start; base < end; base += 32) {
        int cnt = min(32, end - base);
        if (lane < cnt) s_src[warp][lane] = g_csrsrc[base + lane];
        __syncwarp();
        if (lane < cnt) {
            int s = s_src[warp][lane];
            float4 alsv = *(const float4*)&g_als[s * 4];
            s_p[warp][lane * 4 + 0] = __expf(lrelu(alsv.x + aldv.x));
            s_p[warp][lane * 4 + 1] = __expf(lrelu(alsv.y + aldv.y));
            s_p[warp][lane * 4 + 2] = __expf(lrelu(alsv.z + aldv.z));
            s_p[warp][lane * 4 + 3] = __expf(lrelu(alsv.w + aldv.w));
        }
        __syncwarp();
#pragma unroll 4
        for (int e = 0; e < cnt; e++) {
            int s = s_src[warp][e];
            float pe = s_p[warp][e * 4 + hd];
            int4 raw = *(const int4*)&g_hbuf_h[(size_t)s * HC + lane * 8];
            const __half2* hp = (const __half2*)&raw;
            float2 u0 = __half22float2(hp[0]);
            float2 u1 = __half22float2(hp[1]);
            float2 u2 = __half22float2(hp[2]);
            float2 u3 = __half22float2(hp[3]);
            a0 += pe * u0.x; a1 += pe * u0.y; a2 += pe * u1.x; a3 += pe * u1.y;
            a4 += pe * u2.x; a5 += pe * u2.y; a6 += pe * u3.x; a7 += pe * u3.y;
            den += pe;
        }
        __syncwarp();
    }
    float inv = 1.f / den;
    a0 *= inv; a1 *= inv; a2 *= inv; a3 *= inv;
    a4 *= inv; a5 *= inv; a6 *= inv; a7 *= inv;
    // head mean: sum over lanes {l, l^8, l^16, l^24}
#pragma unroll
    for (int o = 8; o <= 16; o <<= 1) {
        a0 += __shfl_xor_sync(0xffffffffu, a0, o);
        a1 += __shfl_xor_sync(0xffffffffu, a1, o);
        a2 += __shfl_xor_sync(0xffffffffu, a2, o);
        a3 += __shfl_xor_sync(0xffffffffu, a3, o);
        a4 += __shfl_xor_sync(0xffffffffu, a4, o);
        a5 += __shfl_xor_sync(0xffffffffu, a5, o);
        a6 += __shfl_xor_sync(0xffffffffu, a6, o);
        a7 += __shfl_xor_sync(0xffffffffu, a7, o);
    }
    if (lane < 8) {
        int c = lane * 8;
        float o0 = a0 * 0.25f + bias[c + 0];
        float o1 = a1 * 0.25f + bias[c + 1];
        float o2 = a2 * 0.25f + bias[c + 2];
        float o3 = a3 * 0.25f + bias[c + 3];
        float o4 = a4 * 0.25f + bias[c + 4];
        float o5 = a5 * 0.25f + bias[c + 5];
        float o6 = a6 * 0.25f + bias[c + 6];
        float o7 = a7 * 0.25f + bias[c + 7];
        if (do_relu) {
            o0 = fmaxf(o0, 0.f); o1 = fmaxf(o1, 0.f); o2 = fmaxf(o2, 0.f); o3 = fmaxf(o3, 0.f);
            o4 = fmaxf(o4, 0.f); o5 = fmaxf(o5, 0.f); o6 = fmaxf(o6, 0.f); o7 = fmaxf(o7, 0.f);
        }
        if (FINAL) {
            float* op = &outf[(size_t)n * CC + c];
            *(float4*)&op[0] = make_float4(o0, o1, o2, o3);
            *(float4*)&op[4] = make_float4(o4, o5, o6, o7);
        } else {
            union { uint4 u; __half2 h[4]; } pk;
            pk.h[0] = __floats2half2_rn(o0, o1);
            pk.h[1] = __floats2half2_rn(o2, o3);
            pk.h[2] = __floats2half2_rn(o4, o5);
            pk.h[3] = __floats2half2_rn(o6, o7);
            *(uint4*)&outh[(size_t)n * CC + c] = pk.u;
        }
    }
}

// ---------------- node-level MLP heads ----------------
__global__ void heads_kernel(const float* __restrict__ emb,
                             const float* __restrict__ aw1, const float* __restrict__ ab1,
                             const float* __restrict__ aw2, const float* __restrict__ ab2,
                             const float* __restrict__ rw1, const float* __restrict__ rb1,
                             const float* __restrict__ rw2, const float* __restrict__ rb2,
                             const float* __restrict__ cw1, const float* __restrict__ cb1,
                             const float* __restrict__ cw2, const float* __restrict__ cb2,
                             float* __restrict__ anom, float* __restrict__ risk,
                             float* __restrict__ res) {
    __shared__ float s_aw1[2048], s_rw1[2048], s_cw1[2048];
    __shared__ float s_aw2[32], s_rw2[32], s_cw2[160];
    __shared__ float s_ab1[32], s_rb1[32], s_cb1[32], s_cb2[5];
    __shared__ float s_ab2, s_rb2;
    for (int i = threadIdx.x; i < 2048; i += blockDim.x) {
        s_aw1[i] = aw1[i];
        s_rw1[i] = rw1[i];
        s_cw1[i] = cw1[i];
    }
    for (int i = threadIdx.x; i < 160; i += blockDim.x) s_cw2[i] = cw2[i];
    if (threadIdx.x < 32) {
        s_aw2[threadIdx.x] = aw2[threadIdx.x];
        s_rw2[threadIdx.x] = rw2[threadIdx.x];
        s_ab1[threadIdx.x] = ab1[threadIdx.x];
        s_rb1[threadIdx.x] = rb1[threadIdx.x];
        s_cb1[threadIdx.x] = cb1[threadIdx.x];
    }
    if (threadIdx.x < 5) s_cb2[threadIdx.x] = cb2[threadIdx.x];
    if (threadIdx.x == 0) { s_ab2 = ab2[0]; s_rb2 = rb2[0]; }
    __syncthreads();

    int n = blockIdx.x * blockDim.x + threadIdx.x;
    if (n >= NN) return;
    float r[64];
    const float4* er = (const float4*)&emb[(size_t)n * 64];
#pragma unroll
    for (int i = 0; i < 16; i++) {
        float4 v = er[i];
        r[i * 4 + 0] = v.x; r[i * 4 + 1] = v.y; r[i * 4 + 2] = v.z; r[i * 4 + 3] = v.w;
    }
    float h[32];
    // anomaly
#pragma unroll
    for (int j = 0; j < 32; j++) h[j] = s_ab1[j];
    for (int k = 0; k < 64; k++) {
        float e = r[k];
#pragma unroll
        for (int j = 0; j < 32; j++) h[j] += e * s_aw1[k * 32 + j];
    }
    float o = s_ab2;
#pragma unroll
    for (int j = 0; j < 32; j++) o += fmaxf(h[j], 0.f) * s_aw2[j];
    anom[n] = 1.f / (1.f + expf(-o));
    // risk
#pragma unroll
    for (int j = 0; j < 32; j++) h[j] = s_rb1[j];
    for (int k = 0; k < 64; k++) {
        float e = r[k];
#pragma unroll
        for (int j = 0; j < 32; j++) h[j] += e * s_rw1[k * 32 + j];
    }
    o = s_rb2;
#pragma unroll
    for (int j = 0; j < 32; j++) o += fmaxf(h[j], 0.f) * s_rw2[j];
    risk[n] = 1.f / (1.f + expf(-o));
    // resource
#pragma unroll
    for (int j = 0; j < 32; j++) h[j] = s_cb1[j];
    for (int k = 0; k < 64; k++) {
        float e = r[k];
#pragma unroll
        for (int j = 0; j < 32; j++) h[j] += e * s_cw1[k * 32 + j];
    }
    float o5[5];
#pragma unroll
    for (int t = 0; t < 5; t++) o5[t] = s_cb2[t];
#pragma unroll
    for (int j = 0; j < 32; j++) {
        float hr = fmaxf(h[j], 0.f);
#pragma unroll
        for (int t = 0; t < 5; t++) o5[t] += hr * s_cw2[j * 5 + t];
    }
#pragma unroll
    for (int t = 0; t < 5; t++) res[(size_t)n * 5 + t] = o5[t];
}

// ---------------- pooling (batch is sorted) ----------------
__global__ void zero_pooled_kernel() {
    int i = blockIdx.x * blockDim.x + threadIdx.x;
    if (i < GG * CC) g_pooled[i] = 0.f;
}

__global__ void pool_kernel(const float* __restrict__ emb, const int* __restrict__ batch) {
    int c = threadIdx.x;  // 64 threads
    int n0 = blockIdx.x * 512;
    int n1 = min(n0 + 512, NN);
    if (n0 >= NN) return;
    int cur = batch[n0];
    float acc = 0.f;
    for (int n = n0; n < n1; n++) {
        int g = batch[n];
        if (g != cur) {
            atomicAdd(&g_pooled[cur * 64 + c], acc);
            acc = 0.f;
            cur = g;
        }
        acc += emb[(size_t)n * 64 + c];
    }
    atomicAdd(&g_pooled[cur * 64 + c], acc);
}

__global__ void graph_kernel(const int* __restrict__ batch,
                             const float* __restrict__ gw1, const float* __restrict__ gb1,
                             const float* __restrict__ gw2, const float* __restrict__ gb2,
                             float* __restrict__ out) {
    int g = threadIdx.x;
    if (g >= GG) return;
    int a = 0, b = NN;
    while (a < b) { int m = (a + b) >> 1; if (batch[m] < g) a = m + 1; else b = m; }
    int lb = a;
    a = 0; b = NN;
    while (a < b) { int m = (a + b) >> 1; if (batch[m] < g + 1) a = m + 1; else b = m; }
    int ub = a;
    float cnt = (float)(ub - lb);
    float inv = 1.f / fmaxf(cnt, 1.f);
    float h[32];
#pragma unroll
    for (int j = 0; j < 32; j++) h[j] = gb1[j];
    for (int k = 0; k < 64; k++) {
        float p = g_pooled[g * 64 + k] * inv;
#pragma unroll
        for (int j = 0; j < 32; j++) h[j] += p * gw1[k * 32 + j];
    }
#pragma unroll
    for (int t = 0; t < 4; t++) {
        float o = gb2[t];
#pragma unroll
        for (int j = 0; j < 32; j++) o += fmaxf(h[j], 0.f) * gw2[j * 4 + t];
        out[g * 4 + t] = o;
    }
}

// ---------------- launcher ----------------
extern "C" void kernel_launch(void* const* d_in, const int* in_sizes, int n_in,
                              void* d_out, int out_size) {
    const float* x = (const float*)d_in[0];
    const int* ei = (const int*)d_in[1];
    const int* batch = (const int*)d_in[2];
    const float* W1 = (const float*)d_in[3];
    const float* as1 = (const float*)d_in[4];
    const float* ad1 = (const float*)d_in[5];
    const float* b1 = (const float*)d_in[6];
    const float* W2 = (const float*)d_in[7];
    const float* as2 = (const float*)d_in[8];
    const float* ad2 = (const float*)d_in[9];
    const float* b2 = (const float*)d_in[10];
    const float* W3 = (const float*)d_in[11];
    const float* as3 = (const float*)d_in[12];
    const float* ad3 = (const float*)d_in[13];
    const float* b3 = (const float*)d_in[14];
    const float* aw1 = (const float*)d_in[15];
    const float* ab1 = (const float*)d_in[16];
    const float* aw2 = (const float*)d_in[17];
    const float* ab2 = (const float*)d_in[18];
    const float* rw1 = (const float*)d_in[19];
    const float* rb1 = (const float*)d_in[20];
    const float* rw2 = (const float*)d_in[21];
    const float* rb2 = (const float*)d_in[22];
    const float* cw1 = (const float*)d_in[23];
    const float* cb1 = (const float*)d_in[24];
    const float* cw2 = (const float*)d_in[25];
    const float* cb2 = (const float*)d_in[26];
    const float* gw1 = (const float*)d_in[27];
    const float* gb1 = (const float*)d_in[28];
    const float* gw2 = (const float*)d_in[29];
    const float* gb2 = (const float*)d_in[30];

    float* out = (float*)d_out;
    float* emb = out + OFF_EMB;
    float* anom = out + OFF_ANOM;
    float* risk = out + OFF_RISK;
    float* res = out + OFF_RES;
    float* glog = out + OFF_GLOG;

    __half* hbuf_p = nullptr;
    __half* acth_p = nullptr;
    __half* xh_p = nullptr;
    __half* w1h_p = nullptr;
    __half* w2h_p = nullptr;
    __half* w3h_p = nullptr;
    cudaGetSymbolAddress((void**)&hbuf_p, g_hbuf_h);
    cudaGetSymbolAddress((void**)&acth_p, g_acth);
    cudaGetSymbolAddress((void**)&xh_p, g_xh);
    cudaGetSymbolAddress((void**)&w1h_p, g_w1h);
    cudaGetSymbolAddress((void**)&w2h_p, g_w2h);
    cudaGetSymbolAddress((void**)&w3h_p, g_w3h);

    // fp16 conversions (x, W1..W3)
    f2h_kernel<<<(NN * 128 / 4 + 255) / 256, 256>>>(x, xh_p, NN * 128 / 4);
    f2h_kernel<<<(128 * HC / 4 + 255) / 256, 256>>>(W1, w1h_p, 128 * HC / 4);
    f2h_kernel<<<(CC * HC / 4 + 255) / 256, 256>>>(W2, w2h_p, CC * HC / 4);
    f2h_kernel<<<(CC * HC / 4 + 255) / 256, 256>>>(W3, w3h_p, CC * HC / 4);

    // CSR build (per-launch, deterministic work)
    zero_cnt_kernel<<<196, 256>>>();
    count_kernel<<<(EE + 255) / 256, 256>>>(ei);
    scan_kernel<<<1, 1024>>>();
    fill_kernel<<<(EE + 255) / 256, 256>>>(ei);

    dim3 wgrid((NN + 127) / 128, 4);

    // Layer 1
    gemm_wmma_kernel<128><<<wgrid, 256>>>(xh_p, w1h_p, hbuf_p, NN);
    al_kernel<<<NN / 8, 256>>>(as1, ad1);
    agg_kernel<0><<<NN / 8, 256>>>(b1, nullptr, acth_p, 1);
    // Layer 2
    gemm_wmma_kernel<64><<<wgrid, 256>>>(acth_p, w2h_p, hbuf_p, NN);
    al_kernel<<<NN / 8, 256>>>(as2, ad2);
    agg_kernel<0><<<NN / 8, 256>>>(b2, nullptr, acth_p, 1);
    // Layer 3 -> emb (in d_out, fp32)
    gemm_wmma_kernel<64><<<wgrid, 256>>>(acth_p, w3h_p, hbuf_p, NN);
    al_kernel<<<NN / 8, 256>>>(as3, ad3);
    agg_kernel<1><<<NN / 8, 256>>>(b3, emb, nullptr, 0);

    // MLP heads
    heads_kernel<<<(NN + 127) / 128, 128>>>(emb, aw1, ab1, aw2, ab2, rw1, rb1, rw2, rb2,
                                            cw1, cb1, cw2, cb2, anom, risk, res);
    // Pooling + graph MLP
    zero_pooled_kernel<<<16, 256>>>();
    pool_kernel<<<(NN + 511) / 512, 64>>>(emb, batch);
    graph_kernel<<<1, 64>>>(batch, gw1, gb1, gw2, gb2, glog);
}

// round 9
// speedup vs baseline: 2.3890x; 1.2548x over previous
#include <cuda_runtime.h>
#include <cuda_fp16.h>
#include <mma.h>
#include <math.h>

// Problem constants (fixed by reference)
#define NN 50000
#define EE 800000
#define HH 4
#define CC 64
#define HC 256   // H*C
#define GG 64
#define NEG 0.2f

// Output layout offsets (emb, anomaly, risk, resource, graph_logits)
#define OFF_EMB   0
#define OFF_ANOM  3200000
#define OFF_RISK  3250000
#define OFF_RES   3300000
#define OFF_GLOG  3550000

// ---------------- device scratch (static, no allocation) ----------------
__device__ __half g_hbuf_h[(size_t)NN * HC];  // per-layer h = act @ W (fp16, 25.6MB)
__device__ __half g_acth[(size_t)NN * CC];    // layer activations (fp16, 6.4MB)
__device__ __half g_xh[(size_t)NN * 128];     // fp16 copy of input x (12.8MB)
__device__ __half g_w1h[128 * HC];
__device__ __half g_w2h[CC * HC];
__device__ __half g_w3h[CC * HC];
__device__ float g_als[NN * HH];
__device__ float g_ald[NN * HH];
__device__ int   g_rowstart[NN + 1];
__device__ int   g_cnt[NN];                   // counts -> cursor (reused)
__device__ int   g_csrsrc[EE];
__device__ float g_pooled[GG * CC];

__device__ __forceinline__ float lrelu(float x) { return x > 0.f ? x : NEG * x; }

// ---------------- fp32 -> fp16 convert ----------------
__global__ void f2h_kernel(const float* __restrict__ src, __half* __restrict__ dst, int n4) {
    int i = blockIdx.x * blockDim.x + threadIdx.x;
    if (i < n4) {
        float4 v = *(const float4*)&src[i * 4];
        union { uint2 u; __half2 h[2]; } pk;
        pk.h[0] = __floats2half2_rn(v.x, v.y);
        pk.h[1] = __floats2half2_rn(v.z, v.w);
        *(uint2*)&dst[i * 4] = pk.u;
    }
}

// ---------------- CSR build ----------------
__global__ void zero_cnt_kernel() {
    int i = blockIdx.x * blockDim.x + threadIdx.x;
    if (i < NN) g_cnt[i] = 0;
}

__global__ void count_kernel(const int* __restrict__ ei) {
    int e = blockIdx.x * blockDim.x + threadIdx.x;
    if (e < EE) atomicAdd(&g_cnt[ei[EE + e]], 1);
}

// single-block exclusive scan of g_cnt -> g_rowstart, also copies into g_cnt (cursor)
__global__ void scan_kernel() {
    __shared__ int wsum[32];
    __shared__ int carry_s;
    if (threadIdx.x == 0) carry_s = 0;
    __syncthreads();
    const int CH = 8192;  // 1024 threads * 8
    for (int base = 0; base < NN; base += CH) {
        int idx0 = base + threadIdx.x * 8;
        int v[8];
        int tot = 0;
#pragma unroll
        for (int i = 0; i < 8; i++) {
            int id = idx0 + i;
            int x = (id < NN) ? g_cnt[id] : 0;
            v[i] = tot;
            tot += x;
        }
        int lane = threadIdx.x & 31, warp = threadIdx.x >> 5;
        int inc = tot;
#pragma unroll
        for (int o = 1; o < 32; o <<= 1) {
            int u = __shfl_up_sync(0xffffffffu, inc, o);
            if (lane >= o) inc += u;
        }
        if (lane == 31) wsum[warp] = inc;
        int excl = inc - tot;
        __syncthreads();
        if (warp == 0) {
            int w = wsum[lane];
            int iw = w;
#pragma unroll
            for (int o = 1; o < 32; o <<= 1) {
                int u = __shfl_up_sync(0xffffffffu, iw, o);
                if (lane >= o) iw += u;
            }
            wsum[lane] = iw - w;
        }
        __syncthreads();
        int off = carry_s + wsum[warp] + excl;
#pragma unroll
        for (int i = 0; i < 8; i++) {
            int id = idx0 + i;
            if (id < NN) {
                int rs = off + v[i];
                g_rowstart[id] = rs;
                g_cnt[id] = rs;  // cursor for fill
            }
        }
        __syncthreads();
        if (threadIdx.x == blockDim.x - 1) carry_s = off + tot;
        __syncthreads();
    }
    if (threadIdx.x == 0) g_rowstart[NN] = EE;
}

__global__ void fill_kernel(const int* __restrict__ ei) {
    int e = blockIdx.x * blockDim.x + threadIdx.x;
    if (e < EE) {
        int dst = ei[EE + e];
        int pos = atomicAdd(&g_cnt[dst], 1);
        g_csrsrc[pos] = ei[e];
    }
}

// ---------------- fused tensor-core GEMM + attention projections ----------------
// C[M,256] = A[M,K]h @ W[K,256]h (fp32 accum -> fp16 out), plus
// als[n][head], ald[n][head] computed from the fp32 accumulators.
// grid: (ceil(M/128), 4=head). block: 256 threads = 8 warps; warp w: rows [w*16, w*16+16).
// Dynamic smem: mainloop = sA[128][K+8] + sW[K][72] halves; epilogue reuses base as
// float stage[8][16*72].
template <int K>
__global__ void gemm_al_kernel(const __half* __restrict__ A, const __half* __restrict__ W,
                               const float* __restrict__ asrc, const float* __restrict__ adst,
                               __half* __restrict__ Ch, int M) {
    using namespace nvcuda;
    extern __shared__ char sm[];
    const int LDA = K + 8;
    __half* sA = (__half*)sm;
    __half* sW = (__half*)(sm + (size_t)128 * LDA * 2);
    __shared__ float s_as[64], s_ad[64];

    int tid = threadIdx.x;
    int w = tid >> 5, lane = tid & 31;
    int head = blockIdx.y;
    int n0 = head * 64;
    int m0 = blockIdx.x * 128;
    int row0 = m0 + w * 16;

    if (tid < 64) {
        s_as[tid] = asrc[head * 64 + tid];
        s_ad[tid] = adst[head * 64 + tid];
    }

    // load A tile: 128 rows x K halves
    const int AV = K / 8;  // uint4 per row
#pragma unroll
    for (int it = 0; it < (128 * AV) / 256; it++) {
        int idx = it * 256 + tid;
        int row = idx / AV, colv = idx % AV;
        uint4 v;
        if (m0 + row < M)
            v = *(const uint4*)&A[(size_t)(m0 + row) * K + colv * 8];
        else
            v = make_uint4(0u, 0u, 0u, 0u);
        *(uint4*)&sA[row * LDA + colv * 8] = v;
    }
    // load W tile: K rows x 64 halves
#pragma unroll
    for (int it = 0; it < (K * 8) / 256; it++) {
        int idx = it * 256 + tid;
        int row = idx >> 3, colv = idx & 7;
        *(uint4*)&sW[row * 72 + colv * 8] = *(const uint4*)&W[(size_t)row * HC + n0 + colv * 8];
    }
    __syncthreads();

    wmma::fragment<wmma::accumulator, 16, 16, 16, float> acc[4];
#pragma unroll
    for (int j = 0; j < 4; j++) wmma::fill_fragment(acc[j], 0.f);
    wmma::fragment<wmma::matrix_a, 16, 16, 16, __half, wmma::row_major> af;
    wmma::fragment<wmma::matrix_b, 16, 16, 16, __half, wmma::row_major> bf;

#pragma unroll
    for (int k0 = 0; k0 < K; k0 += 16) {
        wmma::load_matrix_sync(af, sA + (w * 16) * LDA + k0, LDA);
#pragma unroll
        for (int j = 0; j < 4; j++) {
            wmma::load_matrix_sync(bf, sW + k0 * 72 + j * 16, 72);
            wmma::mma_sync(acc[j], af, bf, acc[j]);
        }
    }
    __syncthreads();  // done with sA/sW; reuse base region as fp32 staging

    float* st = (float*)sm + w * (16 * 72);
#pragma unroll
    for (int j = 0; j < 4; j++)
        wmma::store_matrix_sync(st + j * 16, acc[j], 72, wmma::mem_row_major);
    __syncwarp();

    // store fp16 h
#pragma unroll
    for (int i = lane; i < 512; i += 32) {  // 512 half2 slots in 16x64
        int r = i >> 5, c2 = i & 31;
        if (row0 + r < M) {
            __half2 hv = __floats2half2_rn(st[r * 72 + c2 * 2], st[r * 72 + c2 * 2 + 1]);
            *(__half2*)&Ch[(size_t)(row0 + r) * HC + n0 + c2 * 2] = hv;
        }
    }

    // attention projections: 2 lanes per row, 32 cols each
    {
        int r = lane >> 1, half_ = lane & 1;
        int cb = half_ * 32;
        bool valid = (row0 + r < M);
        float ps = 0.f, pd = 0.f;
        if (valid) {
#pragma unroll
            for (int i = 0; i < 32; i += 4) {
                float4 v = *(const float4*)&st[r * 72 + cb + i];
                float4 a = *(const float4*)&s_as[cb + i];
                float4 d = *(const float4*)&s_ad[cb + i];
                ps += v.x * a.x + v.y * a.y + v.z * a.z + v.w * a.w;
                pd += v.x * d.x + v.y * d.y + v.z * d.z + v.w * d.w;
            }
        }
        ps += __shfl_xor_sync(0xffffffffu, ps, 1);
        pd += __shfl_xor_sync(0xffffffffu, pd, 1);
        if (valid && half_ == 0) {
            g_als[(row0 + r) * 4 + head] = ps;
            g_ald[(row0 + r) * 4 + head] = pd;
        }
    }
}

// ---------------- fused GAT aggregation: softmax + weighted sum + head-mean ----------------
// warp per dst node; lane owns 8 channels (one head each). h gathered as fp16.
// FINAL=0: write fp16 act (g_acth); FINAL=1: write fp32 emb.
template <int FINAL>
__global__ void agg_kernel(const float* __restrict__ bias, float* __restrict__ outf,
                           __half* __restrict__ outh, int do_relu) {
    __shared__ int s_src[8][32];
    __shared__ float s_p[8][32 * 4];
    int warp = threadIdx.x >> 5, lane = threadIdx.x & 31;
    int n = blockIdx.x * 8 + warp;
    if (n >= NN) return;
    int hd = lane >> 3;
    float ald_h = g_ald[n * 4 + hd];
    float als_self = g_als[n * 4 + hd];
    float4 aldv = *(const float4*)&g_ald[n * 4];

    // self-loop
    float p = __expf(lrelu(als_self + ald_h));
    int4 sraw = *(const int4*)&g_hbuf_h[(size_t)n * HC + lane * 8];
    const __half2* sp2 = (const __half2*)&sraw;
    float2 sf0 = __half22float2(sp2[0]);
    float2 sf1 = __half22float2(sp2[1]);
    float2 sf2 = __half22float2(sp2[2]);
    float2 sf3 = __half22float2(sp2[3]);
    float a0 = p * sf0.x, a1 = p * sf0.y, a2 = p * sf1.x, a3 = p * sf1.y;
    float a4 = p * sf2.x, a5 = p * sf2.y, a6 = p * sf3.x, a7 = p * sf3.y;
    float den = p;

    int start = g_rowstart[n], end = g_rowstart[n + 1];
    for (int base = start; base < end; base += 32) {
        int cnt = min(32, end - base);
        if (lane < cnt) s_src[warp][lane] = g_csrsrc[base + lane];
        __syncwarp();
        if (lane < cnt) {
            int s = s_src[warp][lane];
            float4 alsv = *(const float4*)&g_als[s * 4];
            s_p[warp][lane * 4 + 0] = __expf(lrelu(alsv.x + aldv.x));
            s_p[warp][lane * 4 + 1] = __expf(lrelu(alsv.y + aldv.y));
            s_p[warp][lane * 4 + 2] = __expf(lrelu(alsv.z + aldv.z));
            s_p[warp][lane * 4 + 3] = __expf(lrelu(alsv.w + aldv.w));
        }
        __syncwarp();
#pragma unroll 4
        for (int e = 0; e < cnt; e++) {
            int s = s_src[warp][e];
            float pe = s_p[warp][e * 4 + hd];
            int4 raw = *(const int4*)&g_hbuf_h[(size_t)s * HC + lane * 8];
            const __half2* hp = (const __half2*)&raw;
            float2 u0 = __half22float2(hp[0]);
            float2 u1 = __half22float2(hp[1]);
            float2 u2 = __half22float2(hp[2]);
            float2 u3 = __half22float2(hp[3]);
            a0 += pe * u0.x; a1 += pe * u0.y; a2 += pe * u1.x; a3 += pe * u1.y;
            a4 += pe * u2.x; a5 += pe * u2.y; a6 += pe * u3.x; a7 += pe * u3.y;
            den += pe;
        }
        __syncwarp();
    }
    float inv = 1.f / den;
    a0 *= inv; a1 *= inv; a2 *= inv; a3 *= inv;
    a4 *= inv; a5 *= inv; a6 *= inv; a7 *= inv;
    // head mean: sum over lanes {l, l^8, l^16, l^24}
#pragma unroll
    for (int o = 8; o <= 16; o <<= 1) {
        a0 += __shfl_xor_sync(0xffffffffu, a0, o);
        a1 += __shfl_xor_sync(0xffffffffu, a1, o);
        a2 += __shfl_xor_sync(0xffffffffu, a2, o);
        a3 += __shfl_xor_sync(0xffffffffu, a3, o);
        a4 += __shfl_xor_sync(0xffffffffu, a4, o);
        a5 += __shfl_xor_sync(0xffffffffu, a5, o);
        a6 += __shfl_xor_sync(0xffffffffu, a6, o);
        a7 += __shfl_xor_sync(0xffffffffu, a7, o);
    }
    if (lane < 8) {
        int c = lane * 8;
        float o0 = a0 * 0.25f + bias[c + 0];
        float o1 = a1 * 0.25f + bias[c + 1];
        float o2 = a2 * 0.25f + bias[c + 2];
        float o3 = a3 * 0.25f + bias[c + 3];
        float o4 = a4 * 0.25f + bias[c + 4];
        float o5 = a5 * 0.25f + bias[c + 5];
        float o6 = a6 * 0.25f + bias[c + 6];
        float o7 = a7 * 0.25f + bias[c + 7];
        if (do_relu) {
            o0 = fmaxf(o0, 0.f); o1 = fmaxf(o1, 0.f); o2 = fmaxf(o2, 0.f); o3 = fmaxf(o3, 0.f);
            o4 = fmaxf(o4, 0.f); o5 = fmaxf(o5, 0.f); o6 = fmaxf(o6, 0.f); o7 = fmaxf(o7, 0.f);
        }
        if (FINAL) {
            float* op = &outf[(size_t)n * CC + c];
            *(float4*)&op[0] = make_float4(o0, o1, o2, o3);
            *(float4*)&op[4] = make_float4(o4, o5, o6, o7);
        } else {
            union { uint4 u; __half2 h[4]; } pk;
            pk.h[0] = __floats2half2_rn(o0, o1);
            pk.h[1] = __floats2half2_rn(o2, o3);
            pk.h[2] = __floats2half2_rn(o4, o5);
            pk.h[3] = __floats2half2_rn(o6, o7);
            *(uint4*)&outh[(size_t)n * CC + c] = pk.u;
        }
    }
}

// ---------------- node-level MLP heads ----------------
__global__ void heads_kernel(const float* __restrict__ emb,
                             const float* __restrict__ aw1, const float* __restrict__ ab1,
                             const float* __restrict__ aw2, const float* __restrict__ ab2,
                             const float* __restrict__ rw1, const float* __restrict__ rb1,
                             const float* __restrict__ rw2, const float* __restrict__ rb2,
                             const float* __restrict__ cw1, const float* __restrict__ cb1,
                             const float* __restrict__ cw2, const float* __restrict__ cb2,
                             float* __restrict__ anom, float* __restrict__ risk,
                             float* __restrict__ res) {
    __shared__ float s_aw1[2048], s_rw1[2048], s_cw1[2048];
    __shared__ float s_aw2[32], s_rw2[32], s_cw2[160];
    __shared__ float s_ab1[32], s_rb1[32], s_cb1[32], s_cb2[5];
    __shared__ float s_ab2, s_rb2;
    for (int i = threadIdx.x; i < 2048; i += blockDim.x) {
        s_aw1[i] = aw1[i];
        s_rw1[i] = rw1[i];
        s_cw1[i] = cw1[i];
    }
    for (int i = threadIdx.x; i < 160; i += blockDim.x) s_cw2[i] = cw2[i];
    if (threadIdx.x < 32) {
        s_aw2[threadIdx.x] = aw2[threadIdx.x];
        s_rw2[threadIdx.x] = rw2[threadIdx.x];
        s_ab1[threadIdx.x] = ab1[threadIdx.x];
        s_rb1[threadIdx.x] = rb1[threadIdx.x];
        s_cb1[threadIdx.x] = cb1[threadIdx.x];
    }
    if (threadIdx.x < 5) s_cb2[threadIdx.x] = cb2[threadIdx.x];
    if (threadIdx.x == 0) { s_ab2 = ab2[0]; s_rb2 = rb2[0]; }
    __syncthreads();

    int n = blockIdx.x * blockDim.x + threadIdx.x;
    if (n >= NN) return;
    float r[64];
    const float4* er = (const float4*)&emb[(size_t)n * 64];
#pragma unroll
    for (int i = 0; i < 16; i++) {
        float4 v = er[i];
        r[i * 4 + 0] = v.x; r[i * 4 + 1] = v.y; r[i * 4 + 2] = v.z; r[i * 4 + 3] = v.w;
    }
    float h[32];
    // anomaly
#pragma unroll
    for (int j = 0; j < 32; j++) h[j] = s_ab1[j];
    for (int k = 0; k < 64; k++) {
        float e = r[k];
#pragma unroll
        for (int j = 0; j < 32; j++) h[j] += e * s_aw1[k * 32 + j];
    }
    float o = s_ab2;
#pragma unroll
    for (int j = 0; j < 32; j++) o += fmaxf(h[j], 0.f) * s_aw2[j];
    anom[n] = 1.f / (1.f + expf(-o));
    // risk
#pragma unroll
    for (int j = 0; j < 32; j++) h[j] = s_rb1[j];
    for (int k = 0; k < 64; k++) {
        float e = r[k];
#pragma unroll
        for (int j = 0; j < 32; j++) h[j] += e * s_rw1[k * 32 + j];
    }
    o = s_rb2;
#pragma unroll
    for (int j = 0; j < 32; j++) o += fmaxf(h[j], 0.f) * s_rw2[j];
    risk[n] = 1.f / (1.f + expf(-o));
    // resource
#pragma unroll
    for (int j = 0; j < 32; j++) h[j] = s_cb1[j];
    for (int k = 0; k < 64; k++) {
        float e = r[k];
#pragma unroll
        for (int j = 0; j < 32; j++) h[j] += e * s_cw1[k * 32 + j];
    }
    float o5[5];
#pragma unroll
    for (int t = 0; t < 5; t++) o5[t] = s_cb2[t];
#pragma unroll
    for (int j = 0; j < 32; j++) {
        float hr = fmaxf(h[j], 0.f);
#pragma unroll
        for (int t = 0; t < 5; t++) o5[t] += hr * s_cw2[j * 5 + t];
    }
#pragma unroll
    for (int t = 0; t < 5; t++) res[(size_t)n * 5 + t] = o5[t];
}

// ---------------- pooling (batch is sorted) ----------------
__global__ void zero_pooled_kernel() {
    int i = blockIdx.x * blockDim.x + threadIdx.x;
    if (i < GG * CC) g_pooled[i] = 0.f;
}

__global__ void pool_kernel(const float* __restrict__ emb, const int* __restrict__ batch) {
    int c = threadIdx.x;  // 64 threads
    int n0 = blockIdx.x * 512;
    int n1 = min(n0 + 512, NN);
    if (n0 >= NN) return;
    int cur = batch[n0];
    float acc = 0.f;
    for (int n = n0; n < n1; n++) {
        int g = batch[n];
        if (g != cur) {
            atomicAdd(&g_pooled[cur * 64 + c], acc);
            acc = 0.f;
            cur = g;
        }
        acc += emb[(size_t)n * 64 + c];
    }
    atomicAdd(&g_pooled[cur * 64 + c], acc);
}

__global__ void graph_kernel(const int* __restrict__ batch,
                             const float* __restrict__ gw1, const float* __restrict__ gb1,
                             const float* __restrict__ gw2, const float* __restrict__ gb2,
                             float* __restrict__ out) {
    int g = threadIdx.x;
    if (g >= GG) return;
    int a = 0, b = NN;
    while (a < b) { int m = (a + b) >> 1; if (batch[m] < g) a = m + 1; else b = m; }
    int lb = a;
    a = 0; b = NN;
    while (a < b) { int m = (a + b) >> 1; if (batch[m] < g + 1) a = m + 1; else b = m; }
    int ub = a;
    float cnt = (float)(ub - lb);
    float inv = 1.f / fmaxf(cnt, 1.f);
    float h[32];
#pragma unroll
    for (int j = 0; j < 32; j++) h[j] = gb1[j];
    for (int k = 0; k < 64; k++) {
        float p = g_pooled[g * 64 + k] * inv;
#pragma unroll
        for (int j = 0; j < 32; j++) h[j] += p * gw1[k * 32 + j];
    }
#pragma unroll
    for (int t = 0; t < 4; t++) {
        float o = gb2[t];
#pragma unroll
        for (int j = 0; j < 32; j++) o += fmaxf(h[j], 0.f) * gw2[j * 4 + t];
        out[g * 4 + t] = o;
    }
}

// ---------------- launcher ----------------
extern "C" void kernel_launch(void* const* d_in, const int* in_sizes, int n_in,
                              void* d_out, int out_size) {
    const float* x = (const float*)d_in[0];
    const int* ei = (const int*)d_in[1];
    const int* batch = (const int*)d_in[2];
    const float* W1 = (const float*)d_in[3];
    const float* as1 = (const float*)d_in[4];
    const float* ad1 = (const float*)d_in[5];
    const float* b1 = (const float*)d_in[6];
    const float* W2 = (const float*)d_in[7];
    const float* as2 = (const float*)d_in[8];
    const float* ad2 = (const float*)d_in[9];
    const float* b2 = (const float*)d_in[10];
    const float* W3 = (const float*)d_in[11];
    const float* as3 = (const float*)d_in[12];
    const float* ad3 = (const float*)d_in[13];
    const float* b3 = (const float*)d_in[14];
    const float* aw1 = (const float*)d_in[15];
    const float* ab1 = (const float*)d_in[16];
    const float* aw2 = (const float*)d_in[17];
    const float* ab2 = (const float*)d_in[18];
    const float* rw1 = (const float*)d_in[19];
    const float* rb1 = (const float*)d_in[20];
    const float* rw2 = (const float*)d_in[21];
    const float* rb2 = (const float*)d_in[22];
    const float* cw1 = (const float*)d_in[23];
    const float* cb1 = (const float*)d_in[24];
    const float* cw2 = (const float*)d_in[25];
    const float* cb2 = (const float*)d_in[26];
    const float* gw1 = (const float*)d_in[27];
    const float* gb1 = (const float*)d_in[28];
    const float* gw2 = (const float*)d_in[29];
    const float* gb2 = (const float*)d_in[30];

    float* out = (float*)d_out;
    float* emb = out + OFF_EMB;
    float* anom = out + OFF_ANOM;
    float* risk = out + OFF_RISK;
    float* res = out + OFF_RES;
    float* glog = out + OFF_GLOG;

    __half* hbuf_p = nullptr;
    __half* acth_p = nullptr;
    __half* xh_p = nullptr;
    __half* w1h_p = nullptr;
    __half* w2h_p = nullptr;
    __half* w3h_p = nullptr;
    cudaGetSymbolAddress((void**)&hbuf_p, g_hbuf_h);
    cudaGetSymbolAddress((void**)&acth_p, g_acth);
    cudaGetSymbolAddress((void**)&xh_p, g_xh);
    cudaGetSymbolAddress((void**)&w1h_p, g_w1h);
    cudaGetSymbolAddress((void**)&w2h_p, g_w2h);
    cudaGetSymbolAddress((void**)&w3h_p, g_w3h);

    // dynamic smem sizes: K=128 -> max(128*136*2 + 128*72*2, 8*16*72*4) = 53248
    //                     K=64  -> max(128*72*2 + 64*72*2, 8*16*72*4)   = 36864
    const int DS128 = 53248, DS64 = 36864;
    cudaFuncSetAttribute(gemm_al_kernel<128>, cudaFuncAttributeMaxDynamicSharedMemorySize, DS128);

    // fp16 conversions (x, W1..W3)
    f2h_kernel<<<(NN * 128 / 4 + 255) / 256, 256>>>(x, xh_p, NN * 128 / 4);
    f2h_kernel<<<(128 * HC / 4 + 255) / 256, 256>>>(W1, w1h_p, 128 * HC / 4);
    f2h_kernel<<<(CC * HC / 4 + 255) / 256, 256>>>(W2, w2h_p, CC * HC / 4);
    f2h_kernel<<<(CC * HC / 4 + 255) / 256, 256>>>(W3, w3h_p, CC * HC / 4);

    // CSR build (per-launch, deterministic work)
    zero_cnt_kernel<<<196, 256>>>();
    count_kernel<<<(EE + 255) / 256, 256>>>(ei);
    scan_kernel<<<1, 1024>>>();
    fill_kernel<<<(EE + 255) / 256, 256>>>(ei);

    dim3 wgrid((NN + 127) / 128, 4);

    // Layer 1
    gemm_al_kernel<128><<<wgrid, 256, DS128>>>(xh_p, w1h_p, as1, ad1, hbuf_p, NN);
    agg_kernel<0><<<NN / 8, 256>>>(b1, nullptr, acth_p, 1);
    // Layer 2
    gemm_al_kernel<64><<<wgrid, 256, DS64>>>(acth_p, w2h_p, as2, ad2, hbuf_p, NN);
    agg_kernel<0><<<NN / 8, 256>>>(b2, nullptr, acth_p, 1);
    // Layer 3 -> emb (in d_out, fp32)
    gemm_al_kernel<64><<<wgrid, 256, DS64>>>(acth_p, w3h_p, as3, ad3, hbuf_p, NN);
    agg_kernel<1><<<NN / 8, 256>>>(b3, emb, nullptr, 0);

    // MLP heads
    heads_kernel<<<(NN + 127) / 128, 128>>>(emb, aw1, ab1, aw2, ab2, rw1, rb1, rw2, rb2,
                                            cw1, cb1, cw2, cb2, anom, risk, res);
    // Pooling + graph MLP
    zero_pooled_kernel<<<16, 256>>>();
    pool_kernel<<<(NN + 511) / 512, 64>>>(emb, batch);
    graph_kernel<<<1, 64>>>(batch, gw1, gb1, gw2, gb2, glog);
}